// round 5
// baseline (speedup 1.0000x reference)
#include <cuda_runtime.h>
#include <cuda_bf16.h>
#include <math.h>
#include <stdint.h>

// ---------------------------------------------------------------------------
// Problem constants
// ---------------------------------------------------------------------------
#define B_  2
#define T_  2048
#define C_  768
#define H_  12
#define D_  64
#define BH_ (B_*H_)            // 24
#define ROWS_ (B_*T_)          // 4096
#define QKV_ELEMS (BH_*T_*D_)  // 3,145,728
#define W_ELEMS   (C_*C_)
#define Y_ELEMS   (B_*T_*C_)
#define ATT_ELEMS ((size_t)BH_*(size_t)T_*(size_t)T_)
#define SCALE_ 0.125f
#define S_ 40                  // smem tile row stride (bf16 elems)

// Stage layouts (bf16 element offsets within one stage)
#define TILE_ (128*S_)                 // 5120
#define BIG_AH  0
#define BIG_AL  TILE_
#define BIG_BH  (2*TILE_)
#define BIG_BL  (3*TILE_)
#define BIG_STAGE (4*TILE_)            // 20480 elems
#define BIG_SMEM  (3*BIG_STAGE*2)      // 122880 B (3 stages)

#define AV_AH  0
#define AV_AL  TILE_
#define AV_BH  (2*TILE_)
#define AV_BL  (2*TILE_ + 64*S_)
#define AV_STAGE (2*TILE_ + 2*64*S_)   // 15360 elems
#define AV_SMEM  (3*AV_STAGE*2)        // 92160 B

// bf16 hi/lo planes in gmem (same total bytes as the fp32 they replace)
__device__ __nv_bfloat16 g_xh[ROWS_*C_],  g_xl[ROWS_*C_];
__device__ __nv_bfloat16 g_wh[4*W_ELEMS], g_wl[4*W_ELEMS];     // Wq,Wk,Wv,Wp
__device__ __nv_bfloat16 g_qh[QKV_ELEMS], g_ql[QKV_ELEMS];     // [bh][t][d]
__device__ __nv_bfloat16 g_kh[QKV_ELEMS], g_kl[QKV_ELEMS];
__device__ __nv_bfloat16 g_vth[QKV_ELEMS], g_vtl[QKV_ELEMS];   // [bh][d][t]
__device__ __nv_bfloat16 g_yh[Y_ELEMS],  g_yl[Y_ELEMS];        // [b*T+t][h*64+d]
__device__ __nv_bfloat16 g_ph[ATT_ELEMS], g_pl[ATT_ELEMS];     // softmaxed att
__device__ float g_cosT[T_*32], g_sinT[T_*32];

// ---------------------------------------------------------------------------
// PTX helpers
// ---------------------------------------------------------------------------
__device__ __forceinline__ void ldsm4(uint32_t* r, const __nv_bfloat16* p) {
    uint32_t a = (uint32_t)__cvta_generic_to_shared(p);
    asm volatile("ldmatrix.sync.aligned.m8n8.x4.shared.b16 {%0,%1,%2,%3}, [%4];"
        : "=r"(r[0]), "=r"(r[1]), "=r"(r[2]), "=r"(r[3]) : "r"(a));
}
__device__ __forceinline__ void mma_bf16(float* c, const uint32_t* a, const uint32_t* b) {
    asm volatile(
        "mma.sync.aligned.m16n8k16.row.col.f32.bf16.bf16.f32 "
        "{%0,%1,%2,%3}, {%4,%5,%6,%7}, {%8,%9}, {%0,%1,%2,%3};"
        : "+f"(c[0]), "+f"(c[1]), "+f"(c[2]), "+f"(c[3])
        : "r"(a[0]), "r"(a[1]), "r"(a[2]), "r"(a[3]), "r"(b[0]), "r"(b[1]));
}
__device__ __forceinline__ void cpa16(uint32_t dst, const void* src) {
    asm volatile("cp.async.cg.shared.global [%0], [%1], 16;" :: "r"(dst), "l"(src));
}
#define CP_COMMIT() asm volatile("cp.async.commit_group;")
#define CP_WAIT1()  asm volatile("cp.async.wait_group 1;")

// Issue one 128x32 bf16 plane into smem (padded stride S_). 2 x 16B per thread.
__device__ __forceinline__ void is_t128(uint32_t sbase, const __nv_bfloat16* g,
                                        int stride, int tid) {
    const int row = tid >> 1, c0 = (tid & 1) * 16;
    const char* src = (const char*)(g + (size_t)row * stride + c0);
    const uint32_t dst = sbase + (uint32_t)(row * S_ + c0) * 2u;
    cpa16(dst, src);
    cpa16(dst + 16, src + 16);
}
// Issue one 64x32 bf16 plane. 1 x 16B per thread.
__device__ __forceinline__ void is_t64(uint32_t sbase, const __nv_bfloat16* g,
                                       int stride, int tid) {
    const int row = tid >> 2, c0 = (tid & 3) * 8;
    cpa16(sbase + (uint32_t)(row * S_ + c0) * 2u,
          g + (size_t)row * stride + c0);
}

// ---------------------------------------------------------------------------
// Core: one BK=32 chunk of split-bf16 MMA. Warp tile = 32(M) x (NF*8)(N).
// ---------------------------------------------------------------------------
template<int NF>
__device__ __forceinline__ void compute_chunk(
    const __nv_bfloat16* __restrict__ sAh, const __nv_bfloat16* __restrict__ sAl,
    const __nv_bfloat16* __restrict__ sBh, const __nv_bfloat16* __restrict__ sBl,
    int wm0, int wn0, int lane, float (*acc)[4])
{
    const int ar = lane & 15, acs = (lane >> 4) << 3;
    const int br = (lane & 7) + ((lane >> 4) << 3), bcs = ((lane >> 3) & 1) << 3;
    #pragma unroll
    for (int ks = 0; ks < 2; ks++) {
        const int k0 = ks << 4;
        uint32_t ah0[4], ah1[4], al0[4], al1[4];
        ldsm4(ah0, sAh + (wm0 + ar) * S_ + k0 + acs);
        ldsm4(ah1, sAh + (wm0 + 16 + ar) * S_ + k0 + acs);
        ldsm4(al0, sAl + (wm0 + ar) * S_ + k0 + acs);
        ldsm4(al1, sAl + (wm0 + 16 + ar) * S_ + k0 + acs);
        #pragma unroll
        for (int ng = 0; ng < NF / 2; ng++) {
            const int n0 = wn0 + (ng << 4);
            uint32_t bh[4], bl[4];
            ldsm4(bh, sBh + (n0 + br) * S_ + k0 + bcs);
            ldsm4(bl, sBl + (n0 + br) * S_ + k0 + bcs);
            #pragma unroll
            for (int mi = 0; mi < 2; mi++) {
                const uint32_t* am = mi ? ah1 : ah0;
                const uint32_t* alm = mi ? al1 : al0;
                float* cA = acc[mi * NF + ng * 2];
                float* cB = acc[mi * NF + ng * 2 + 1];
                mma_bf16(cA, am, bh);     mma_bf16(cA, am, bl);     mma_bf16(cA, alm, bh);
                mma_bf16(cB, am, bh + 2); mma_bf16(cB, am, bl + 2); mma_bf16(cB, alm, bh + 2);
            }
        }
    }
}

// ---------------------------------------------------------------------------
// K0a: RoPE trig tables
// ---------------------------------------------------------------------------
__global__ __launch_bounds__(256) void trig_kernel()
{
    int idx = blockIdx.x * 256 + threadIdx.x;
    if (idx >= T_ * 32) return;
    int t = idx >> 5, j = idx & 31;
    const float inv = (float)pow(10000.0, -(double)j / 32.0);
    const float ang = (float)t * inv;
    g_cosT[idx] = cosf(ang);
    g_sinT[idx] = sinf(ang);
}

// K0b: fp32 -> bf16 hi/lo planes (vectorized)
__global__ __launch_bounds__(256) void split4_kernel(
    const float4* __restrict__ src, __nv_bfloat162* __restrict__ dh,
    __nv_bfloat162* __restrict__ dl, int n4)
{
    int i = blockIdx.x * 256 + threadIdx.x;
    if (i >= n4) return;
    float4 f = src[i];
    __nv_bfloat162 h0 = __floats2bfloat162_rn(f.x, f.y);
    __nv_bfloat162 h1 = __floats2bfloat162_rn(f.z, f.w);
    __nv_bfloat162 l0 = __floats2bfloat162_rn(f.x - __bfloat162float(h0.x),
                                              f.y - __bfloat162float(h0.y));
    __nv_bfloat162 l1 = __floats2bfloat162_rn(f.z - __bfloat162float(h1.x),
                                              f.w - __bfloat162float(h1.y));
    dh[2*i] = h0; dh[2*i+1] = h1;
    dl[2*i] = l0; dl[2*i+1] = l1;
}

// ---------------------------------------------------------------------------
// K1: QKV projection. cp.async 3-stage; epilogue RoPE + plane stores.
// ---------------------------------------------------------------------------
__global__ __launch_bounds__(256) void qkv_mma()
{
    extern __shared__ __align__(16) __nv_bfloat16 sm[];
    const uint32_t sb = (uint32_t)__cvta_generic_to_shared(sm);
    const int tid = threadIdx.x, lane = tid & 31, wid = tid >> 5;
    const int wm = wid & 3, wn = wid >> 2;
    const int z = blockIdx.z;
    const int row0 = blockIdx.y * 128, col0 = blockIdx.x * 128;
    const __nv_bfloat16* Ah = g_xh + (size_t)row0 * C_;
    const __nv_bfloat16* Al = g_xl + (size_t)row0 * C_;
    const __nv_bfloat16* Bh = g_wh + (size_t)z * W_ELEMS + (size_t)col0 * C_;
    const __nv_bfloat16* Bl = g_wl + (size_t)z * W_ELEMS + (size_t)col0 * C_;

    float acc[16][4];
    #pragma unroll
    for (int i = 0; i < 16; i++)
        #pragma unroll
        for (int j = 0; j < 4; j++) acc[i][j] = 0.0f;

    const int nch = 24;
    #pragma unroll
    for (int p = 0; p < 2; p++) {
        const uint32_t st = sb + (uint32_t)(p * BIG_STAGE) * 2u;
        is_t128(st + BIG_AH*2, Ah + p*32, C_, tid);
        is_t128(st + BIG_AL*2, Al + p*32, C_, tid);
        is_t128(st + BIG_BH*2, Bh + p*32, C_, tid);
        is_t128(st + BIG_BL*2, Bl + p*32, C_, tid);
        CP_COMMIT();
    }
    for (int c = 0; c < nch; c++) {
        CP_WAIT1();
        __syncthreads();
        if (c + 2 < nch) {
            const uint32_t st = sb + (uint32_t)(((c + 2) % 3) * BIG_STAGE) * 2u;
            is_t128(st + BIG_AH*2, Ah + (c+2)*32, C_, tid);
            is_t128(st + BIG_AL*2, Al + (c+2)*32, C_, tid);
            is_t128(st + BIG_BH*2, Bh + (c+2)*32, C_, tid);
            is_t128(st + BIG_BL*2, Bl + (c+2)*32, C_, tid);
        }
        CP_COMMIT();
        const __nv_bfloat16* cur = sm + (c % 3) * BIG_STAGE;
        compute_chunk<8>(cur + BIG_AH, cur + BIG_AL, cur + BIG_BH, cur + BIG_BL,
                         wm * 32, wn * 64, lane, acc);
    }

    const int g = lane >> 2, tg2 = (lane & 3) << 1;
    const int rowB = row0 + wm * 32, colB = col0 + wn * 64;

    if (z < 2) {  // RoPE on first 32 dims of each head
        #pragma unroll
        for (int mi = 0; mi < 2; mi++)
            #pragma unroll
            for (int ci = 0; ci < 4; ci++) {
                const int row = rowB + mi * 16 + g + (ci >> 1) * 8;
                const int t = row & (T_ - 1);
                const int e = ci & 1;
                #pragma unroll
                for (int nf = 0; nf < 2; nf++) {
                    const int d0 = nf * 8 + tg2 + e;
                    const float c0 = g_cosT[t * 32 + d0],      s0 = g_sinT[t * 32 + d0];
                    const float c1 = g_cosT[t * 32 + d0 + 16], s1 = g_sinT[t * 32 + d0 + 16];
                    const float u0 = acc[mi * 8 + nf][ci];
                    const float u1 = acc[mi * 8 + nf + 2][ci];
                    acc[mi * 8 + nf][ci]     = u0 * c0 - u1 * s0;
                    acc[mi * 8 + nf + 2][ci] = fmaf(u1, c1, u0 * s1);
                }
            }
    }

    __nv_bfloat16* dh = (z == 0) ? g_qh : g_kh;
    __nv_bfloat16* dl = (z == 0) ? g_ql : g_kl;
    #pragma unroll
    for (int mi = 0; mi < 2; mi++)
        #pragma unroll
        for (int half = 0; half < 2; half++) {
            const int row = rowB + mi * 16 + g + half * 8;
            const int b = row >> 11, t = row & (T_ - 1);
            #pragma unroll
            for (int nf = 0; nf < 8; nf++) {
                const int col = colB + nf * 8 + tg2;
                const int h = col >> 6, d = col & 63;
                const int bh = b * H_ + h;
                const float v0 = acc[mi * 8 + nf][half * 2];
                const float v1 = acc[mi * 8 + nf][half * 2 + 1];
                __nv_bfloat162 hv = __floats2bfloat162_rn(v0, v1);
                __nv_bfloat162 lv = __floats2bfloat162_rn(v0 - __bfloat162float(hv.x),
                                                          v1 - __bfloat162float(hv.y));
                if (z == 2) {
                    const size_t o = ((size_t)(bh * D_ + d)) * T_ + t;
                    g_vth[o] = hv.x;       g_vtl[o] = lv.x;
                    g_vth[o + T_] = hv.y;  g_vtl[o + T_] = lv.y;
                } else {
                    const size_t base = ((size_t)bh * T_ + t) * D_ + d;
                    *(__nv_bfloat162*)(dh + base) = hv;
                    *(__nv_bfloat162*)(dl + base) = lv;
                }
            }
        }
}

// ---------------------------------------------------------------------------
// K2: causal scores. Lower-tri 128x128 tiles, K=64 (2 chunks).
// ---------------------------------------------------------------------------
__global__ __launch_bounds__(256) void scores_mma(
    const float* __restrict__ rel_bias, float* __restrict__ att)
{
    extern __shared__ __align__(16) __nv_bfloat16 sm[];
    __shared__ float bias_s[256];
    const uint32_t sb = (uint32_t)__cvta_generic_to_shared(sm);
    const int tid = threadIdx.x, lane = tid & 31, wid = tid >> 5;
    const int wm = wid & 3, wn = wid >> 2;

    int p = blockIdx.x, qt = 0;
    while ((qt + 1) * (qt + 2) / 2 <= p) qt++;
    const int kt = p - qt * (qt + 1) / 2;
    const int bh = blockIdx.y, h = bh % H_;
    const int q0 = qt * 128, k0 = kt * 128;

    const __nv_bfloat16* Ah = g_qh + ((size_t)bh * T_ + q0) * D_;
    const __nv_bfloat16* Al = g_ql + ((size_t)bh * T_ + q0) * D_;
    const __nv_bfloat16* Bh = g_kh + ((size_t)bh * T_ + k0) * D_;
    const __nv_bfloat16* Bl = g_kl + ((size_t)bh * T_ + k0) * D_;

    #pragma unroll
    for (int pp = 0; pp < 2; pp++) {
        const uint32_t st = sb + (uint32_t)(pp * BIG_STAGE) * 2u;
        is_t128(st + BIG_AH*2, Ah + pp*32, D_, tid);
        is_t128(st + BIG_AL*2, Al + pp*32, D_, tid);
        is_t128(st + BIG_BH*2, Bh + pp*32, D_, tid);
        is_t128(st + BIG_BL*2, Bl + pp*32, D_, tid);
        CP_COMMIT();
    }
    if (tid < 255)
        bias_s[tid] = rel_bias[(size_t)((q0 - k0) + tid - 127 + (T_ - 1)) * H_ + h];

    float acc[16][4];
    #pragma unroll
    for (int i = 0; i < 16; i++)
        #pragma unroll
        for (int j = 0; j < 4; j++) acc[i][j] = 0.0f;

    for (int c = 0; c < 2; c++) {
        CP_WAIT1();
        __syncthreads();
        CP_COMMIT();
        const __nv_bfloat16* cur = sm + c * BIG_STAGE;
        compute_chunk<8>(cur + BIG_AH, cur + BIG_AL, cur + BIG_BH, cur + BIG_BL,
                         wm * 32, wn * 64, lane, acc);
    }

    const int g = lane >> 2, tg2 = (lane & 3) << 1;
    #pragma unroll
    for (int mi = 0; mi < 2; mi++)
        #pragma unroll
        for (int half = 0; half < 2; half++) {
            const int qi = q0 + wm * 32 + mi * 16 + g + half * 8;
            #pragma unroll
            for (int nf = 0; nf < 8; nf++) {
                const int ki = k0 + wn * 64 + nf * 8 + tg2;
                const int dd = qi - ki - q0 + k0 + 127;
                const float v0 = (ki <= qi)
                    ? fmaf(acc[mi * 8 + nf][half * 2], SCALE_, bias_s[dd]) : -1e30f;
                const float v1 = (ki + 1 <= qi)
                    ? fmaf(acc[mi * 8 + nf][half * 2 + 1], SCALE_, bias_s[dd - 1]) : -1e30f;
                *(float2*)(att + ((size_t)bh * T_ + qi) * T_ + ki) = make_float2(v0, v1);
            }
        }
}

// ---------------------------------------------------------------------------
// K3: row softmax, float4 streaming; emits fp32 att + bf16 p-planes.
// ---------------------------------------------------------------------------
__global__ __launch_bounds__(256) void softmax_kernel(float* __restrict__ att)
{
    const int row = blockIdx.x;
    const int q = row & (T_ - 1);
    const int n4 = (((q >> 7) + 1) << 7) >> 2;   // kend/4
    float4* p4 = (float4*)(att + (size_t)row * T_);
    const size_t off = (size_t)row * T_;

    __shared__ float4 buf[T_/4];
    __shared__ float smax[8], ssum[8];
    const int tid = threadIdx.x, lane = tid & 31, wrp = tid >> 5;

    float m = -1e30f;
    for (int i = tid; i < n4; i += 256) {
        const float4 f = p4[i];
        buf[i] = f;
        m = fmaxf(fmaxf(m, fmaxf(f.x, f.y)), fmaxf(f.z, f.w));
    }
    #pragma unroll
    for (int o = 16; o > 0; o >>= 1)
        m = fmaxf(m, __shfl_xor_sync(0xffffffffu, m, o));
    if (lane == 0) smax[wrp] = m;
    __syncthreads();
    m = smax[0];
    #pragma unroll
    for (int w = 1; w < 8; w++) m = fmaxf(m, smax[w]);

    float sum = 0.0f;
    for (int i = tid; i < n4; i += 256) {
        float4 f = buf[i];
        f.x = __expf(f.x - m); f.y = __expf(f.y - m);
        f.z = __expf(f.z - m); f.w = __expf(f.w - m);
        buf[i] = f;
        sum += (f.x + f.y) + (f.z + f.w);
    }
    #pragma unroll
    for (int o = 16; o > 0; o >>= 1)
        sum += __shfl_xor_sync(0xffffffffu, sum, o);
    if (lane == 0) ssum[wrp] = sum;
    __syncthreads();
    sum = ssum[0];
    #pragma unroll
    for (int w = 1; w < 8; w++) sum += ssum[w];
    const float inv = 1.0f / sum;

    for (int i = tid; i < n4; i += 256) {
        float4 f = buf[i];
        f.x *= inv; f.y *= inv; f.z *= inv; f.w *= inv;
        p4[i] = f;
        __nv_bfloat162 h0 = __floats2bfloat162_rn(f.x, f.y);
        __nv_bfloat162 h1 = __floats2bfloat162_rn(f.z, f.w);
        __nv_bfloat162 l0 = __floats2bfloat162_rn(f.x - __bfloat162float(h0.x),
                                                  f.y - __bfloat162float(h0.y));
        __nv_bfloat162 l1 = __floats2bfloat162_rn(f.z - __bfloat162float(h1.x),
                                                  f.w - __bfloat162float(h1.y));
        __nv_bfloat16* ph = g_ph + off + 4 * i;
        __nv_bfloat16* pl = g_pl + off + 4 * i;
        ((__nv_bfloat162*)ph)[0] = h0; ((__nv_bfloat162*)ph)[1] = h1;
        ((__nv_bfloat162*)pl)[0] = l0; ((__nv_bfloat162*)pl)[1] = l1;
    }
    const float4 z4 = make_float4(0.f, 0.f, 0.f, 0.f);
    for (int i = n4 + tid; i < T_/4; i += 256)
        p4[i] = z4;
}

// ---------------------------------------------------------------------------
// K4: y = att @ v. cp.async 3-stage; causal K range; y planes out.
// ---------------------------------------------------------------------------
__global__ __launch_bounds__(256) void av_mma()
{
    extern __shared__ __align__(16) __nv_bfloat16 sm[];
    const uint32_t sb = (uint32_t)__cvta_generic_to_shared(sm);
    const int tid = threadIdx.x, lane = tid & 31, wid = tid >> 5;
    const int wm = wid & 3, wn = wid >> 2;
    const int qt = blockIdx.x, bh = blockIdx.y;
    const int q0 = qt * 128;
    const int nch = 4 * (qt + 1);

    const __nv_bfloat16* Ah = g_ph + ((size_t)bh * T_ + q0) * T_;
    const __nv_bfloat16* Al = g_pl + ((size_t)bh * T_ + q0) * T_;
    const __nv_bfloat16* Bh = g_vth + (size_t)bh * D_ * T_;
    const __nv_bfloat16* Bl = g_vtl + (size_t)bh * D_ * T_;

    float acc[8][4];
    #pragma unroll
    for (int i = 0; i < 8; i++)
        #pragma unroll
        for (int j = 0; j < 4; j++) acc[i][j] = 0.0f;

    #pragma unroll
    for (int p = 0; p < 2; p++) {
        const uint32_t st = sb + (uint32_t)(p * AV_STAGE) * 2u;
        is_t128(st + AV_AH*2, Ah + p*32, T_, tid);
        is_t128(st + AV_AL*2, Al + p*32, T_, tid);
        is_t64 (st + AV_BH*2, Bh + p*32, T_, tid);
        is_t64 (st + AV_BL*2, Bl + p*32, T_, tid);
        CP_COMMIT();
    }
    for (int c = 0; c < nch; c++) {
        CP_WAIT1();
        __syncthreads();
        if (c + 2 < nch) {
            const uint32_t st = sb + (uint32_t)(((c + 2) % 3) * AV_STAGE) * 2u;
            is_t128(st + AV_AH*2, Ah + (c+2)*32, T_, tid);
            is_t128(st + AV_AL*2, Al + (c+2)*32, T_, tid);
            is_t64 (st + AV_BH*2, Bh + (c+2)*32, T_, tid);
            is_t64 (st + AV_BL*2, Bl + (c+2)*32, T_, tid);
        }
        CP_COMMIT();
        const __nv_bfloat16* cur = sm + (c % 3) * AV_STAGE;
        compute_chunk<4>(cur + AV_AH, cur + AV_AL, cur + AV_BH, cur + AV_BL,
                         wm * 32, wn * 32, lane, acc);
    }

    const int g = lane >> 2, tg2 = (lane & 3) << 1;
    const int b = bh / H_, h = bh % H_;
    #pragma unroll
    for (int mi = 0; mi < 2; mi++)
        #pragma unroll
        for (int half = 0; half < 2; half++) {
            const int t = q0 + wm * 32 + mi * 16 + g + half * 8;
            #pragma unroll
            for (int nf = 0; nf < 4; nf++) {
                const int d = wn * 32 + nf * 8 + tg2;
                const float v0 = acc[mi * 4 + nf][half * 2];
                const float v1 = acc[mi * 4 + nf][half * 2 + 1];
                __nv_bfloat162 hv = __floats2bfloat162_rn(v0, v1);
                __nv_bfloat162 lv = __floats2bfloat162_rn(v0 - __bfloat162float(hv.x),
                                                          v1 - __bfloat162float(hv.y));
                const size_t base = ((size_t)(b * T_ + t)) * C_ + h * D_ + d;
                *(__nv_bfloat162*)(g_yh + base) = hv;
                *(__nv_bfloat162*)(g_yl + base) = lv;
            }
        }
}

// ---------------------------------------------------------------------------
// K5: output projection + bias. cp.async 3-stage.
// ---------------------------------------------------------------------------
__global__ __launch_bounds__(256) void proj_mma(
    const float* __restrict__ bp, float* __restrict__ out)
{
    extern __shared__ __align__(16) __nv_bfloat16 sm[];
    const uint32_t sb = (uint32_t)__cvta_generic_to_shared(sm);
    const int tid = threadIdx.x, lane = tid & 31, wid = tid >> 5;
    const int wm = wid & 3, wn = wid >> 2;
    const int row0 = blockIdx.y * 128, col0 = blockIdx.x * 128;
    const __nv_bfloat16* Ah = g_yh + (size_t)row0 * C_;
    const __nv_bfloat16* Al = g_yl + (size_t)row0 * C_;
    const __nv_bfloat16* Bh = g_wh + 3 * (size_t)W_ELEMS + (size_t)col0 * C_;
    const __nv_bfloat16* Bl = g_wl + 3 * (size_t)W_ELEMS + (size_t)col0 * C_;

    float acc[16][4];
    #pragma unroll
    for (int i = 0; i < 16; i++)
        #pragma unroll
        for (int j = 0; j < 4; j++) acc[i][j] = 0.0f;

    const int nch = 24;
    #pragma unroll
    for (int p = 0; p < 2; p++) {
        const uint32_t st = sb + (uint32_t)(p * BIG_STAGE) * 2u;
        is_t128(st + BIG_AH*2, Ah + p*32, C_, tid);
        is_t128(st + BIG_AL*2, Al + p*32, C_, tid);
        is_t128(st + BIG_BH*2, Bh + p*32, C_, tid);
        is_t128(st + BIG_BL*2, Bl + p*32, C_, tid);
        CP_COMMIT();
    }
    for (int c = 0; c < nch; c++) {
        CP_WAIT1();
        __syncthreads();
        if (c + 2 < nch) {
            const uint32_t st = sb + (uint32_t)(((c + 2) % 3) * BIG_STAGE) * 2u;
            is_t128(st + BIG_AH*2, Ah + (c+2)*32, C_, tid);
            is_t128(st + BIG_AL*2, Al + (c+2)*32, C_, tid);
            is_t128(st + BIG_BH*2, Bh + (c+2)*32, C_, tid);
            is_t128(st + BIG_BL*2, Bl + (c+2)*32, C_, tid);
        }
        CP_COMMIT();
        const __nv_bfloat16* cur = sm + (c % 3) * BIG_STAGE;
        compute_chunk<8>(cur + BIG_AH, cur + BIG_AL, cur + BIG_BH, cur + BIG_BL,
                         wm * 32, wn * 64, lane, acc);
    }

    const int g = lane >> 2, tg2 = (lane & 3) << 1;
    #pragma unroll
    for (int mi = 0; mi < 2; mi++)
        #pragma unroll
        for (int half = 0; half < 2; half++) {
            const int row = row0 + wm * 32 + mi * 16 + g + half * 8;
            #pragma unroll
            for (int nf = 0; nf < 8; nf++) {
                const int col = col0 + wn * 64 + nf * 8 + tg2;
                const float v0 = acc[mi * 8 + nf][half * 2] + __ldg(&bp[col]);
                const float v1 = acc[mi * 8 + nf][half * 2 + 1] + __ldg(&bp[col + 1]);
                *(float2*)(out + (size_t)row * C_ + col) = make_float2(v0, v1);
            }
        }
}

// ---------------------------------------------------------------------------
// Launch
// ---------------------------------------------------------------------------
extern "C" void kernel_launch(void* const* d_in, const int* in_sizes, int n_in,
                              void* d_out, int out_size)
{
    const float* x        = (const float*)d_in[0];
    const float* Wq       = (const float*)d_in[1];
    const float* Wk       = (const float*)d_in[2];
    const float* Wv       = (const float*)d_in[3];
    const float* Wp       = (const float*)d_in[4];
    const float* bp       = (const float*)d_in[5];
    const float* rel_bias = (const float*)d_in[6];

    float* y_out = (float*)d_out;
    float* att   = (float*)d_out + Y_ELEMS;

    cudaFuncSetAttribute(qkv_mma,    cudaFuncAttributeMaxDynamicSharedMemorySize, BIG_SMEM);
    cudaFuncSetAttribute(scores_mma, cudaFuncAttributeMaxDynamicSharedMemorySize, BIG_SMEM);
    cudaFuncSetAttribute(av_mma,     cudaFuncAttributeMaxDynamicSharedMemorySize, AV_SMEM);
    cudaFuncSetAttribute(proj_mma,   cudaFuncAttributeMaxDynamicSharedMemorySize, BIG_SMEM);

    __nv_bfloat16 *xh, *xl, *wh, *wl;
    cudaGetSymbolAddress((void**)&xh, g_xh);
    cudaGetSymbolAddress((void**)&xl, g_xl);
    cudaGetSymbolAddress((void**)&wh, g_wh);
    cudaGetSymbolAddress((void**)&wl, g_wl);

    trig_kernel<<<(T_ * 32 + 255) / 256, 256>>>();
    {
        int n4 = ROWS_ * C_ / 4;
        split4_kernel<<<(n4 + 255) / 256, 256>>>((const float4*)x,
            (__nv_bfloat162*)xh, (__nv_bfloat162*)xl, n4);
        int w4 = W_ELEMS / 4;
        const float* Ws[4] = {Wq, Wk, Wv, Wp};
        for (int z = 0; z < 4; z++)
            split4_kernel<<<(w4 + 255) / 256, 256>>>((const float4*)Ws[z],
                (__nv_bfloat162*)(wh + (size_t)z * W_ELEMS),
                (__nv_bfloat162*)(wl + (size_t)z * W_ELEMS), w4);
    }
    qkv_mma<<<dim3(C_ / 128, ROWS_ / 128, 3), 256, BIG_SMEM>>>();
    scores_mma<<<dim3(136, BH_), 256, BIG_SMEM>>>(rel_bias, att);
    softmax_kernel<<<BH_ * T_, 256>>>(att);
    av_mma<<<dim3(T_ / 128, BH_), 256, AV_SMEM>>>();
    proj_mma<<<dim3(C_ / 128, ROWS_ / 128), 256, BIG_SMEM>>>(bp, y_out);
}

// round 6
// speedup vs baseline: 1.2101x; 1.2101x over previous
#include <cuda_runtime.h>
#include <cuda_fp16.h>
#include <math.h>
#include <stdint.h>

// ---------------------------------------------------------------------------
// Problem constants
// ---------------------------------------------------------------------------
#define B_  2
#define T_  2048
#define C_  768
#define H_  12
#define D_  64
#define BH_ (B_*H_)            // 24
#define ROWS_ (B_*T_)          // 4096
#define QKV_ELEMS (BH_*T_*D_)  // 3,145,728
#define Y_ELEMS   (B_*T_*C_)
#define SCALE_ 0.125f
#define S_ 40                  // smem tile row stride (fp16 elems), mult of 8

// fp32 intermediates (device globals; no allocation allowed)
__device__ float g_q[QKV_ELEMS];    // [bh][t][d]
__device__ float g_k[QKV_ELEMS];    // [bh][t][d]
__device__ float g_vt[QKV_ELEMS];   // [bh][d][t]
__device__ float g_y[Y_ELEMS];      // [b*T+t][h*64+d]
__device__ float g_cosT[T_*32], g_sinT[T_*32];

// ---------------------------------------------------------------------------
// HMMA helpers (arch-agnostic: mma.sync + ldmatrix)
// ---------------------------------------------------------------------------
__device__ __forceinline__ void ldsm4(uint32_t* r, const __half* p) {
    uint32_t a = (uint32_t)__cvta_generic_to_shared(p);
    asm volatile("ldmatrix.sync.aligned.m8n8.x4.shared.b16 {%0,%1,%2,%3}, [%4];"
        : "=r"(r[0]), "=r"(r[1]), "=r"(r[2]), "=r"(r[3]) : "r"(a));
}
__device__ __forceinline__ void mma_f16(float* c, const uint32_t* a, const uint32_t* b) {
    asm volatile(
        "mma.sync.aligned.m16n8k16.row.col.f32.f16.f16.f32 "
        "{%0,%1,%2,%3}, {%4,%5,%6,%7}, {%8,%9}, {%0,%1,%2,%3};"
        : "+f"(c[0]), "+f"(c[1]), "+f"(c[2]), "+f"(c[3])
        : "r"(a[0]), "r"(a[1]), "r"(a[2]), "r"(a[3]), "r"(b[0]), "r"(b[1]));
}

// ---------------------------------------------------------------------------
// Tile movement: gmem fp32 -> regs -> convert -> smem fp16
// 128-row x 32-col tile, 256 threads: each thread 16 floats.
// ---------------------------------------------------------------------------
__device__ __forceinline__ void ld_t128(float4* r, const float* src, int stride, int tid) {
    const float* s = src + (size_t)(tid >> 1) * stride + ((tid & 1) << 4);
    #pragma unroll
    for (int v = 0; v < 4; v++) r[v] = ((const float4*)s)[v];
}
// A-side: hi/lo fp16 split
__device__ __forceinline__ void st_t128hl(const float4* r, __half* hi, __half* lo, int tid) {
    const int row = tid >> 1, c0 = (tid & 1) << 4;
    __half* ph = hi + row * S_ + c0;
    __half* pl = lo + row * S_ + c0;
    #pragma unroll
    for (int v = 0; v < 4; v++) {
        float4 f = r[v];
        __half2 h0 = __floats2half2_rn(f.x, f.y);
        __half2 h1 = __floats2half2_rn(f.z, f.w);
        __half2 l0 = __floats2half2_rn(f.x - __half2float(__low2half(h0)),
                                       f.y - __half2float(__high2half(h0)));
        __half2 l1 = __floats2half2_rn(f.z - __half2float(__low2half(h1)),
                                       f.w - __half2float(__high2half(h1)));
        ((__half2*)(ph + v * 4))[0] = h0;
        ((__half2*)(ph + v * 4))[1] = h1;
        ((__half2*)(pl + v * 4))[0] = l0;
        ((__half2*)(pl + v * 4))[1] = l1;
    }
}
// B-side: single fp16
__device__ __forceinline__ void st_t128s(const float4* r, __half* dst, int tid) {
    const int row = tid >> 1, c0 = (tid & 1) << 4;
    __half* p = dst + row * S_ + c0;
    #pragma unroll
    for (int v = 0; v < 4; v++) {
        float4 f = r[v];
        ((__half2*)(p + v * 4))[0] = __floats2half2_rn(f.x, f.y);
        ((__half2*)(p + v * 4))[1] = __floats2half2_rn(f.z, f.w);
    }
}
// 64x32 variants (av B tile)
__device__ __forceinline__ void ld_t64(float4* r, const float* src, int stride, int tid) {
    const float* s = src + (size_t)(tid >> 2) * stride + ((tid & 3) << 3);
    r[0] = ((const float4*)s)[0];
    r[1] = ((const float4*)s)[1];
}
__device__ __forceinline__ void st_t64s(const float4* r, __half* dst, int tid) {
    const int row = tid >> 2, c0 = (tid & 3) << 3;
    __half* p = dst + row * S_ + c0;
    #pragma unroll
    for (int v = 0; v < 2; v++) {
        float4 f = r[v];
        ((__half2*)(p + v * 4))[0] = __floats2half2_rn(f.x, f.y);
        ((__half2*)(p + v * 4))[1] = __floats2half2_rn(f.z, f.w);
    }
}

// ---------------------------------------------------------------------------
// Core: one BK=32 chunk, 2-term fp16 MMA: Ah*B + Al*B.
// Warp tile = 32(M) x (NF*8)(N).
// ---------------------------------------------------------------------------
template<int NF>
__device__ __forceinline__ void compute_chunk2(
    const __half* __restrict__ sAh, const __half* __restrict__ sAl,
    const __half* __restrict__ sB,
    int wm0, int wn0, int lane, float (*acc)[4])
{
    const int ar = lane & 15, acs = (lane >> 4) << 3;
    const int br = (lane & 7) + ((lane >> 4) << 3), bcs = ((lane >> 3) & 1) << 3;
    #pragma unroll
    for (int ks = 0; ks < 2; ks++) {
        const int k0 = ks << 4;
        uint32_t ah0[4], ah1[4], al0[4], al1[4];
        ldsm4(ah0, sAh + (wm0 + ar) * S_ + k0 + acs);
        ldsm4(ah1, sAh + (wm0 + 16 + ar) * S_ + k0 + acs);
        ldsm4(al0, sAl + (wm0 + ar) * S_ + k0 + acs);
        ldsm4(al1, sAl + (wm0 + 16 + ar) * S_ + k0 + acs);
        #pragma unroll
        for (int ng = 0; ng < NF / 2; ng++) {
            const int n0 = wn0 + (ng << 4);
            uint32_t bh[4];
            ldsm4(bh, sB + (n0 + br) * S_ + k0 + bcs);
            #pragma unroll
            for (int mi = 0; mi < 2; mi++) {
                const uint32_t* am = mi ? ah1 : ah0;
                const uint32_t* alm = mi ? al1 : al0;
                float* cA = acc[mi * NF + ng * 2];
                float* cB = acc[mi * NF + ng * 2 + 1];
                mma_f16(cA, am, bh);     mma_f16(cA, alm, bh);
                mma_f16(cB, am, bh + 2); mma_f16(cB, alm, bh + 2);
            }
        }
    }
}

// ---------------------------------------------------------------------------
// K0: RoPE trig tables
// ---------------------------------------------------------------------------
__global__ __launch_bounds__(256) void trig_kernel()
{
    int idx = blockIdx.x * 256 + threadIdx.x;
    if (idx >= T_ * 32) return;
    int t = idx >> 5, j = idx & 31;
    const float inv = (float)pow(10000.0, -(double)j / 32.0);
    const float ang = (float)t * inv;
    g_cosT[idx] = cosf(ang);
    g_sinT[idx] = sinf(ang);
}

// ---------------------------------------------------------------------------
// K1: QKV projection (2-term fp16). 128x128 tile, K=768.
// ---------------------------------------------------------------------------
__global__ __launch_bounds__(256) void qkv_mma(
    const float* __restrict__ x, const float* __restrict__ Wq,
    const float* __restrict__ Wk, const float* __restrict__ Wv)
{
    __shared__ __half sAh[128*S_], sAl[128*S_], sB[128*S_];
    const int tid = threadIdx.x, lane = tid & 31, wid = tid >> 5;
    const int wm = wid & 3, wn = wid >> 2;
    const int z = blockIdx.z;
    const int row0 = blockIdx.y * 128, col0 = blockIdx.x * 128;
    const float* W = (z == 0) ? Wq : (z == 1) ? Wk : Wv;

    float acc[16][4];
    #pragma unroll
    for (int i = 0; i < 16; i++)
        #pragma unroll
        for (int j = 0; j < 4; j++) acc[i][j] = 0.0f;

    float4 ra[4], rb[4];
    ld_t128(ra, x + (size_t)row0 * C_, C_, tid);
    ld_t128(rb, W + (size_t)col0 * C_, C_, tid);
    for (int c = 0; c < 24; c++) {
        st_t128hl(ra, sAh, sAl, tid);
        st_t128s(rb, sB, tid);
        __syncthreads();
        if (c < 23) {
            ld_t128(ra, x + (size_t)row0 * C_ + (c + 1) * 32, C_, tid);
            ld_t128(rb, W + (size_t)col0 * C_ + (c + 1) * 32, C_, tid);
        }
        compute_chunk2<8>(sAh, sAl, sB, wm * 32, wn * 64, lane, acc);
        __syncthreads();
    }

    const int g = lane >> 2, tg2 = (lane & 3) << 1;
    const int rowB = row0 + wm * 32, colB = col0 + wn * 64;

    if (z < 2) {  // RoPE on first 32 dims of each head
        #pragma unroll
        for (int mi = 0; mi < 2; mi++)
            #pragma unroll
            for (int ci = 0; ci < 4; ci++) {
                const int row = rowB + mi * 16 + g + (ci >> 1) * 8;
                const int t = row & (T_ - 1);
                const int e = ci & 1;
                #pragma unroll
                for (int nf = 0; nf < 2; nf++) {
                    const int d0 = nf * 8 + tg2 + e;
                    const float c0 = g_cosT[t * 32 + d0],      s0 = g_sinT[t * 32 + d0];
                    const float c1 = g_cosT[t * 32 + d0 + 16], s1 = g_sinT[t * 32 + d0 + 16];
                    const float u0 = acc[mi * 8 + nf][ci];
                    const float u1 = acc[mi * 8 + nf + 2][ci];
                    acc[mi * 8 + nf][ci]     = u0 * c0 - u1 * s0;
                    acc[mi * 8 + nf + 2][ci] = fmaf(u1, c1, u0 * s1);
                }
            }
    }

    float* dst = (z == 0) ? g_q : g_k;
    #pragma unroll
    for (int mi = 0; mi < 2; mi++)
        #pragma unroll
        for (int half = 0; half < 2; half++) {
            const int row = rowB + mi * 16 + g + half * 8;
            const int b = row >> 11, t = row & (T_ - 1);
            #pragma unroll
            for (int nf = 0; nf < 8; nf++) {
                const int col = colB + nf * 8 + tg2;
                const int h = col >> 6, d = col & 63;
                const int bh = b * H_ + h;
                const float v0 = acc[mi * 8 + nf][half * 2];
                const float v1 = acc[mi * 8 + nf][half * 2 + 1];
                if (z == 2) {
                    g_vt[((size_t)(bh * D_ + d)) * T_ + t] = v0;
                    g_vt[((size_t)(bh * D_ + d + 1)) * T_ + t] = v1;
                } else {
                    *(float2*)(dst + ((size_t)bh * T_ + t) * D_ + d) = make_float2(v0, v1);
                }
            }
        }
}

// ---------------------------------------------------------------------------
// K2: causal scores (2-term fp16). Lower-tri 128x128 tiles, K=64.
// ---------------------------------------------------------------------------
__global__ __launch_bounds__(256) void scores_mma(
    const float* __restrict__ rel_bias, float* __restrict__ att)
{
    __shared__ __half sAh[128*S_], sAl[128*S_], sB[128*S_];
    __shared__ float bias_s[256];
    const int tid = threadIdx.x, lane = tid & 31, wid = tid >> 5;
    const int wm = wid & 3, wn = wid >> 2;

    int p = blockIdx.x, qt = 0;
    while ((qt + 1) * (qt + 2) / 2 <= p) qt++;
    const int kt = p - qt * (qt + 1) / 2;
    const int bh = blockIdx.y, h = bh % H_;
    const int q0 = qt * 128, k0 = kt * 128;

    if (tid < 255)
        bias_s[tid] = rel_bias[(size_t)((q0 - k0) + tid - 127 + (T_ - 1)) * H_ + h];

    const float* qsrc = g_q + ((size_t)bh * T_ + q0) * D_;
    const float* ksrc = g_k + ((size_t)bh * T_ + k0) * D_;

    float acc[16][4];
    #pragma unroll
    for (int i = 0; i < 16; i++)
        #pragma unroll
        for (int j = 0; j < 4; j++) acc[i][j] = 0.0f;

    float4 ra[4], rb[4];
    ld_t128(ra, qsrc, D_, tid);
    ld_t128(rb, ksrc, D_, tid);
    for (int c = 0; c < 2; c++) {
        st_t128hl(ra, sAh, sAl, tid);
        st_t128s(rb, sB, tid);
        __syncthreads();
        if (c == 0) {
            ld_t128(ra, qsrc + 32, D_, tid);
            ld_t128(rb, ksrc + 32, D_, tid);
        }
        compute_chunk2<8>(sAh, sAl, sB, wm * 32, wn * 64, lane, acc);
        __syncthreads();
    }

    const int g = lane >> 2, tg2 = (lane & 3) << 1;
    #pragma unroll
    for (int mi = 0; mi < 2; mi++)
        #pragma unroll
        for (int half = 0; half < 2; half++) {
            const int qi = q0 + wm * 32 + mi * 16 + g + half * 8;
            #pragma unroll
            for (int nf = 0; nf < 8; nf++) {
                const int ki = k0 + wn * 64 + nf * 8 + tg2;
                const int dd = qi - ki - q0 + k0 + 127;
                const float v0 = (ki <= qi)
                    ? fmaf(acc[mi * 8 + nf][half * 2], SCALE_, bias_s[dd]) : -1e30f;
                const float v1 = (ki + 1 <= qi)
                    ? fmaf(acc[mi * 8 + nf][half * 2 + 1], SCALE_, bias_s[dd - 1]) : -1e30f;
                *(float2*)(att + ((size_t)bh * T_ + qi) * T_ + ki) = make_float2(v0, v1);
            }
        }
}

// ---------------------------------------------------------------------------
// K3: row softmax — branch-free float4 streaming over [0, kend), zero tail.
// ---------------------------------------------------------------------------
__global__ __launch_bounds__(256) void softmax_kernel(float* __restrict__ att)
{
    const int row = blockIdx.x;
    const int q = row & (T_ - 1);
    const int n4 = (((q >> 7) + 1) << 7) >> 2;   // kend/4, 32..512
    float4* p4 = (float4*)(att + (size_t)row * T_);

    __shared__ float4 buf[T_/4];
    __shared__ float smax[8], ssum[8];
    const int tid = threadIdx.x, lane = tid & 31, wrp = tid >> 5;

    float m = -1e30f;
    for (int i = tid; i < n4; i += 256) {
        const float4 f = p4[i];
        buf[i] = f;
        m = fmaxf(fmaxf(m, fmaxf(f.x, f.y)), fmaxf(f.z, f.w));
    }
    #pragma unroll
    for (int o = 16; o > 0; o >>= 1)
        m = fmaxf(m, __shfl_xor_sync(0xffffffffu, m, o));
    if (lane == 0) smax[wrp] = m;
    __syncthreads();
    m = smax[0];
    #pragma unroll
    for (int w = 1; w < 8; w++) m = fmaxf(m, smax[w]);

    float sum = 0.0f;
    for (int i = tid; i < n4; i += 256) {
        float4 f = buf[i];
        f.x = __expf(f.x - m); f.y = __expf(f.y - m);
        f.z = __expf(f.z - m); f.w = __expf(f.w - m);
        buf[i] = f;
        sum += (f.x + f.y) + (f.z + f.w);
    }
    #pragma unroll
    for (int o = 16; o > 0; o >>= 1)
        sum += __shfl_xor_sync(0xffffffffu, sum, o);
    if (lane == 0) ssum[wrp] = sum;
    __syncthreads();
    sum = ssum[0];
    #pragma unroll
    for (int w = 1; w < 8; w++) sum += ssum[w];
    const float inv = 1.0f / sum;

    for (int i = tid; i < n4; i += 256) {
        float4 f = buf[i];
        f.x *= inv; f.y *= inv; f.z *= inv; f.w *= inv;
        p4[i] = f;
    }
    const float4 z4 = make_float4(0.f, 0.f, 0.f, 0.f);
    for (int i = n4 + tid; i < T_/4; i += 256)
        p4[i] = z4;
}

// ---------------------------------------------------------------------------
// K4: y = att @ v (2-term fp16). Block 128(q) x 64(d); causal K range.
// ---------------------------------------------------------------------------
__global__ __launch_bounds__(256) void av_mma(const float* __restrict__ att)
{
    __shared__ __half sAh[128*S_], sAl[128*S_], sB[64*S_];
    const int tid = threadIdx.x, lane = tid & 31, wid = tid >> 5;
    const int wm = wid & 3, wn = wid >> 2;
    const int qt = blockIdx.x, bh = blockIdx.y;
    const int q0 = qt * 128;
    const int nch = 4 * (qt + 1);

    const float* asrc = att + ((size_t)bh * T_ + q0) * T_;
    const float* bsrc = g_vt + (size_t)bh * D_ * T_;

    float acc[8][4];
    #pragma unroll
    for (int i = 0; i < 8; i++)
        #pragma unroll
        for (int j = 0; j < 4; j++) acc[i][j] = 0.0f;

    float4 ra[4], rb[2];
    ld_t128(ra, asrc, T_, tid);
    ld_t64(rb, bsrc, T_, tid);
    for (int c = 0; c < nch; c++) {
        st_t128hl(ra, sAh, sAl, tid);
        st_t64s(rb, sB, tid);
        __syncthreads();
        if (c + 1 < nch) {
            ld_t128(ra, asrc + (c + 1) * 32, T_, tid);
            ld_t64(rb, bsrc + (c + 1) * 32, T_, tid);
        }
        compute_chunk2<4>(sAh, sAl, sB, wm * 32, wn * 32, lane, acc);
        __syncthreads();
    }

    const int g = lane >> 2, tg2 = (lane & 3) << 1;
    const int b = bh / H_, h = bh % H_;
    #pragma unroll
    for (int mi = 0; mi < 2; mi++)
        #pragma unroll
        for (int half = 0; half < 2; half++) {
            const int t = q0 + wm * 32 + mi * 16 + g + half * 8;
            #pragma unroll
            for (int nf = 0; nf < 4; nf++) {
                const int d = wn * 32 + nf * 8 + tg2;
                *(float2*)(g_y + ((size_t)(b * T_ + t)) * C_ + h * D_ + d) =
                    make_float2(acc[mi * 4 + nf][half * 2], acc[mi * 4 + nf][half * 2 + 1]);
            }
        }
}

// ---------------------------------------------------------------------------
// K5: output projection (2-term fp16) + bias.
// ---------------------------------------------------------------------------
__global__ __launch_bounds__(256) void proj_mma(
    const float* __restrict__ Wp, const float* __restrict__ bp,
    float* __restrict__ out)
{
    __shared__ __half sAh[128*S_], sAl[128*S_], sB[128*S_];
    const int tid = threadIdx.x, lane = tid & 31, wid = tid >> 5;
    const int wm = wid & 3, wn = wid >> 2;
    const int row0 = blockIdx.y * 128, col0 = blockIdx.x * 128;

    float acc[16][4];
    #pragma unroll
    for (int i = 0; i < 16; i++)
        #pragma unroll
        for (int j = 0; j < 4; j++) acc[i][j] = 0.0f;

    float4 ra[4], rb[4];
    ld_t128(ra, g_y + (size_t)row0 * C_, C_, tid);
    ld_t128(rb, Wp + (size_t)col0 * C_, C_, tid);
    for (int c = 0; c < 24; c++) {
        st_t128hl(ra, sAh, sAl, tid);
        st_t128s(rb, sB, tid);
        __syncthreads();
        if (c < 23) {
            ld_t128(ra, g_y + (size_t)row0 * C_ + (c + 1) * 32, C_, tid);
            ld_t128(rb, Wp + (size_t)col0 * C_ + (c + 1) * 32, C_, tid);
        }
        compute_chunk2<8>(sAh, sAl, sB, wm * 32, wn * 64, lane, acc);
        __syncthreads();
    }

    const int g = lane >> 2, tg2 = (lane & 3) << 1;
    #pragma unroll
    for (int mi = 0; mi < 2; mi++)
        #pragma unroll
        for (int half = 0; half < 2; half++) {
            const int row = row0 + wm * 32 + mi * 16 + g + half * 8;
            #pragma unroll
            for (int nf = 0; nf < 8; nf++) {
                const int col = col0 + wn * 64 + nf * 8 + tg2;
                const float v0 = acc[mi * 8 + nf][half * 2] + __ldg(&bp[col]);
                const float v1 = acc[mi * 8 + nf][half * 2 + 1] + __ldg(&bp[col + 1]);
                *(float2*)(out + (size_t)row * C_ + col) = make_float2(v0, v1);
            }
        }
}

// ---------------------------------------------------------------------------
// Launch
// ---------------------------------------------------------------------------
extern "C" void kernel_launch(void* const* d_in, const int* in_sizes, int n_in,
                              void* d_out, int out_size)
{
    const float* x        = (const float*)d_in[0];
    const float* Wq       = (const float*)d_in[1];
    const float* Wk       = (const float*)d_in[2];
    const float* Wv       = (const float*)d_in[3];
    const float* Wp       = (const float*)d_in[4];
    const float* bp       = (const float*)d_in[5];
    const float* rel_bias = (const float*)d_in[6];

    float* y_out = (float*)d_out;
    float* att   = (float*)d_out + Y_ELEMS;

    trig_kernel<<<(T_ * 32 + 255) / 256, 256>>>();
    qkv_mma<<<dim3(C_ / 128, ROWS_ / 128, 3), 256>>>(x, Wq, Wk, Wv);
    scores_mma<<<dim3(136, BH_), 256>>>(rel_bias, att);
    softmax_kernel<<<BH_ * T_, 256>>>(att);
    av_mma<<<dim3(T_ / 128, BH_), 256>>>(att);
    proj_mma<<<dim3(C_ / 128, ROWS_ / 128), 256>>>(Wp, bp, y_out);
}